// round 1
// baseline (speedup 1.0000x reference)
#include <cuda_runtime.h>
#include <math.h>

#define NB  4
#define TI  512
#define TO  64
#define TO1 65
#define VV  1024
#define EE  512
#define HH  512
#define JJ  512
#define G4  2048                 // 4*H
#define M_SEQ (NB*TO1)           // 260
#define M_OUT (NB*TI*TO1)        // 133120

// Scratch (device globals -- no allocation allowed)
__device__ float g_xa[M_SEQ*EE];
__device__ float g_xb[M_SEQ*HH];
__device__ float g_xg[M_SEQ*G4];
__device__ float g_hs[NB*HH];
__device__ float g_cs[NB*HH];
__device__ float g_encp[NB*TI*JJ];
__device__ float g_decp[M_SEQ*JJ];

// ---------------------------------------------------------------------------
// Embedding with prepended blank token
// ---------------------------------------------------------------------------
__global__ void k_embed(const int* __restrict__ tgt, const float* __restrict__ emb,
                        float* __restrict__ x) {
    int idx = blockIdx.x*blockDim.x + threadIdx.x;
    if (idx >= M_SEQ*EE) return;
    int e = idx & (EE-1);
    int m = idx >> 9;                  // EE = 512
    int n = m / TO1, t = m - n*TO1;
    int tok = (t == 0) ? 0 : tgt[n*TO + t - 1];
    x[idx] = emb[tok*EE + e];
}

__global__ void k_zero_state() {
    int i = blockIdx.x*blockDim.x + threadIdx.x;
    if (i < NB*HH) { g_hs[i] = 0.f; g_cs[i] = 0.f; }
}

// ---------------------------------------------------------------------------
// Generic C[m,n] = sum_k A[m,k]*B[n,k] + b1[n] + b2[n]
// 64x64x16 tiles, 256 threads, 4x4 microtile. N,K multiples of 64/16; M guarded.
// ---------------------------------------------------------------------------
__global__ void k_gemm_abT(const float* __restrict__ A, const float* __restrict__ B,
                           const float* __restrict__ b1, const float* __restrict__ b2,
                           float* __restrict__ C, int M, int Nn, int K) {
    __shared__ float As[16][64];
    __shared__ float Bs[16][64];
    const int tid = threadIdx.x;
    const int m0 = blockIdx.x*64, n0 = blockIdx.y*64;
    const int lr = tid >> 2;            // 0..63
    const int lk = (tid & 3) << 2;      // 0,4,8,12
    const int tx = tid & 15, ty = tid >> 4;
    float acc[4][4] = {};
    const bool mval = (m0 + lr) < M;
    const float* Ap = A + (size_t)(m0+lr)*K + lk;
    const float* Bp = B + (size_t)(n0+lr)*K + lk;

    for (int k0 = 0; k0 < K; k0 += 16) {
        float4 av = make_float4(0.f,0.f,0.f,0.f);
        if (mval) av = *(const float4*)(Ap + k0);
        float4 bv = *(const float4*)(Bp + k0);
        As[lk+0][lr]=av.x; As[lk+1][lr]=av.y; As[lk+2][lr]=av.z; As[lk+3][lr]=av.w;
        Bs[lk+0][lr]=bv.x; Bs[lk+1][lr]=bv.y; Bs[lk+2][lr]=bv.z; Bs[lk+3][lr]=bv.w;
        __syncthreads();
#pragma unroll
        for (int k = 0; k < 16; k++) {
            float4 a4 = *(const float4*)&As[k][ty*4];
            float4 b4 = *(const float4*)&Bs[k][tx*4];
            float aa[4] = {a4.x,a4.y,a4.z,a4.w};
            float bb[4] = {b4.x,b4.y,b4.z,b4.w};
#pragma unroll
            for (int i=0;i<4;i++)
#pragma unroll
                for (int j=0;j<4;j++) acc[i][j] += aa[i]*bb[j];
        }
        __syncthreads();
    }
    float bias[4];
#pragma unroll
    for (int j=0;j<4;j++) {
        int nn = n0 + tx*4 + j;
        bias[j] = (b1 ? b1[nn] : 0.f) + (b2 ? b2[nn] : 0.f);
    }
#pragma unroll
    for (int i=0;i<4;i++) {
        int m = m0 + ty*4 + i;
        if (m < M) {
            float4 o = make_float4(acc[i][0]+bias[0], acc[i][1]+bias[1],
                                   acc[i][2]+bias[2], acc[i][3]+bias[3]);
            *(float4*)&C[(size_t)m*Nn + n0 + tx*4] = o;
        }
    }
}

// ---------------------------------------------------------------------------
// One LSTM timestep. Block = 16 hidden units x (4 gates x 4 batches).
// Warp-per-row dot (coalesced Whh reads), all 4 batches per pass, fused
// gate nonlinearity + (h,c) update. Grid = 512/16 = 32 blocks.
// ---------------------------------------------------------------------------
__device__ __forceinline__ float sigf(float x) { return 1.f/(1.f + expf(-x)); }

__global__ void k_lstm_step(const float* __restrict__ xg, const float* __restrict__ Whh,
                            float* __restrict__ xout, int t) {
    __shared__ float sh[NB*HH];          // all 4 batches' h (8 KB)
    __shared__ float gsm[4][NB][16];     // [gate][batch][hidden-in-block]
    const int tid = threadIdx.x;
    for (int i = tid; i < NB*HH; i += 256) sh[i] = g_hs[i];
    __syncthreads();

    const int warp = tid >> 5, lane = tid & 31;
    const int j0 = blockIdx.x * 16;
#pragma unroll
    for (int r = 0; r < 8; r++) {
        int rl = warp*8 + r;             // 0..63
        int q  = rl >> 4, jj = rl & 15;  // gate, hidden-local
        int row = q*HH + j0 + jj;
        const float4* wp = (const float4*)(Whh + (size_t)row*HH);
        float a0=0.f, a1=0.f, a2=0.f, a3=0.f;
#pragma unroll
        for (int it = 0; it < 4; it++) {
            int kv = it*32 + lane;
            float4 w  = wp[kv];
            float4 h0 = *(const float4*)&sh[0*HH + kv*4];
            float4 h1 = *(const float4*)&sh[1*HH + kv*4];
            float4 h2 = *(const float4*)&sh[2*HH + kv*4];
            float4 h3 = *(const float4*)&sh[3*HH + kv*4];
            a0 += w.x*h0.x + w.y*h0.y + w.z*h0.z + w.w*h0.w;
            a1 += w.x*h1.x + w.y*h1.y + w.z*h1.z + w.w*h1.w;
            a2 += w.x*h2.x + w.y*h2.y + w.z*h2.z + w.w*h2.w;
            a3 += w.x*h3.x + w.y*h3.y + w.z*h3.z + w.w*h3.w;
        }
#pragma unroll
        for (int off = 16; off; off >>= 1) {
            a0 += __shfl_down_sync(0xffffffffu, a0, off);
            a1 += __shfl_down_sync(0xffffffffu, a1, off);
            a2 += __shfl_down_sync(0xffffffffu, a2, off);
            a3 += __shfl_down_sync(0xffffffffu, a3, off);
        }
        if (lane == 0) {
            gsm[q][0][jj]=a0; gsm[q][1][jj]=a1; gsm[q][2][jj]=a2; gsm[q][3][jj]=a3;
        }
    }
    __syncthreads();
    if (tid < 64) {
        int b = tid >> 4, jj = tid & 15, j = j0 + jj;
        const float* xp = xg + (size_t)(b*TO1 + t)*G4;
        float pi = gsm[0][b][jj] + xp[0*HH + j];
        float pf = gsm[1][b][jj] + xp[1*HH + j];
        float pg = gsm[2][b][jj] + xp[2*HH + j];
        float po = gsm[3][b][jj] + xp[3*HH + j];
        float iv = sigf(pi), fv = sigf(pf), gv = tanhf(pg), ov = sigf(po);
        float c = fv * g_cs[b*HH + j] + iv * gv;
        float h = ov * tanhf(c);
        g_cs[b*HH + j] = c;
        g_hs[b*HH + j] = h;
        xout[(size_t)(b*TO1 + t)*HH + j] = h;
    }
}

// ---------------------------------------------------------------------------
// Final fused kernel: out[m, v] = sum_j tanh(encp[n,t,j] + decp[n,u,j]) * outw[v,j]
// m = (n*TI + t)*TO1 + u.  128x128x8 tiles, 256 threads, 8x8 microtile.
// M_OUT=133120 and VV=1024 divide tiles exactly -> no guards.
// ---------------------------------------------------------------------------
__global__ void k_gemm_out(const float* __restrict__ encp, const float* __restrict__ decp,
                           const float* __restrict__ outw, float* __restrict__ out) {
    __shared__ float As[8][128];
    __shared__ float Bs[8][128];
    const int tid = threadIdx.x;
    const int m0 = blockIdx.x * 128;
    const int v0 = blockIdx.y * 128;
    const int lm = tid >> 1;             // 0..127
    const int lk = (tid & 1) << 2;       // 0 or 4
    // decode (n, t, u) once -- fixed per thread across k-loop
    const int m   = m0 + lm;
    const int n   = m / (TI*TO1);
    const int rem = m - n*(TI*TO1);
    const int t   = rem / TO1;
    const int u   = rem - t*TO1;
    const float* ep = encp + (size_t)(n*TI + t)*JJ + lk;
    const float* dp = decp + (size_t)(n*TO1 + u)*JJ + lk;
    const float* bp = outw + (size_t)(v0 + lm)*JJ + lk;
    const int tx = tid & 15, ty = tid >> 4;
    float acc[8][8] = {};

    for (int k0 = 0; k0 < JJ; k0 += 8) {
        float4 e4 = *(const float4*)(ep + k0);
        float4 d4 = *(const float4*)(dp + k0);
        As[lk+0][lm] = tanhf(e4.x + d4.x);
        As[lk+1][lm] = tanhf(e4.y + d4.y);
        As[lk+2][lm] = tanhf(e4.z + d4.z);
        As[lk+3][lm] = tanhf(e4.w + d4.w);
        float4 b4 = *(const float4*)(bp + k0);
        Bs[lk+0][lm] = b4.x; Bs[lk+1][lm] = b4.y; Bs[lk+2][lm] = b4.z; Bs[lk+3][lm] = b4.w;
        __syncthreads();
#pragma unroll
        for (int k = 0; k < 8; k++) {
            float a[8], b[8];
            *(float4*)&a[0] = *(const float4*)&As[k][ty*8];
            *(float4*)&a[4] = *(const float4*)&As[k][ty*8+4];
            *(float4*)&b[0] = *(const float4*)&Bs[k][tx*8];
            *(float4*)&b[4] = *(const float4*)&Bs[k][tx*8+4];
#pragma unroll
            for (int i=0;i<8;i++)
#pragma unroll
                for (int j=0;j<8;j++) acc[i][j] += a[i]*b[j];
        }
        __syncthreads();
    }
#pragma unroll
    for (int i=0;i<8;i++) {
        size_t mm = (size_t)(m0 + ty*8 + i);
        float* op = out + mm*VV + v0 + tx*8;
        *(float4*)(op)   = make_float4(acc[i][0],acc[i][1],acc[i][2],acc[i][3]);
        *(float4*)(op+4) = make_float4(acc[i][4],acc[i][5],acc[i][6],acc[i][7]);
    }
}

// ---------------------------------------------------------------------------
extern "C" void kernel_launch(void* const* d_in, const int* in_sizes, int n_in,
                              void* d_out, int out_size) {
    const float* enc_out = (const float*)d_in[0];
    const int*   tgt     = (const int*)  d_in[1];
    const float* emb     = (const float*)d_in[2];
    const float* Wih[3]  = {(const float*)d_in[3],  (const float*)d_in[7],  (const float*)d_in[11]};
    const float* Whh[3]  = {(const float*)d_in[4],  (const float*)d_in[8],  (const float*)d_in[12]};
    const float* bih[3]  = {(const float*)d_in[5],  (const float*)d_in[9],  (const float*)d_in[13]};
    const float* bhh[3]  = {(const float*)d_in[6],  (const float*)d_in[10], (const float*)d_in[14]};
    const float* enc_w   = (const float*)d_in[15];
    const float* dec_w   = (const float*)d_in[16];
    const float* dec_b   = (const float*)d_in[17];
    const float* out_w   = (const float*)d_in[18];
    float* out = (float*)d_out;

    float *xa, *xb, *xg, *encp, *decp;
    cudaGetSymbolAddress((void**)&xa,   g_xa);
    cudaGetSymbolAddress((void**)&xb,   g_xb);
    cudaGetSymbolAddress((void**)&xg,   g_xg);
    cudaGetSymbolAddress((void**)&encp, g_encp);
    cudaGetSymbolAddress((void**)&decp, g_decp);

    // 1) embedding
    k_embed<<<(M_SEQ*EE + 255)/256, 256>>>(tgt, emb, xa);

    // 2) 3 LSTM layers
    float* cur = xa;
    float* nxt = xb;
    for (int l = 0; l < 3; l++) {
        dim3 gxg((M_SEQ + 63)/64, G4/64);
        k_gemm_abT<<<gxg, 256>>>(cur, Wih[l], bih[l], bhh[l], xg, M_SEQ, G4, HH);
        k_zero_state<<<(NB*HH + 255)/256, 256>>>();
        for (int t = 0; t < TO1; t++)
            k_lstm_step<<<HH/16, 256>>>(xg, Whh[l], nxt, t);
        float* tmp = cur; cur = nxt; nxt = tmp;
    }

    // 3) enc_p, dec_p projections
    {
        dim3 g((NB*TI)/64, JJ/64);
        k_gemm_abT<<<g, 256>>>(enc_out, enc_w, nullptr, nullptr, encp, NB*TI, JJ, 512);
    }
    {
        dim3 g((M_SEQ + 63)/64, JJ/64);
        k_gemm_abT<<<g, 256>>>(cur, dec_w, dec_b, nullptr, decp, M_SEQ, JJ, HH);
    }

    // 4) fused tanh(joint) @ out_w^T
    {
        dim3 g(M_OUT/128, VV/128);
        k_gemm_out<<<g, 256>>>(encp, decp, out_w, out);
    }
}

// round 2
// speedup vs baseline: 1.2089x; 1.2089x over previous
#include <cuda_runtime.h>
#include <math.h>

#define NB  4
#define TI  512
#define TO  64
#define TO1 65
#define VV  1024
#define EE  512
#define HH  512
#define JJ  512
#define G4  2048                 // 4*H
#define M_SEQ (NB*TO1)           // 260
#define M_OUT (NB*TI*TO1)        // 133120
#define NTICK (TO1 + 2)          // wavefront depth: 67
#define GRID_LSTM 96             // 3 layers x 32 blocks; <= 148 SMs => all co-resident

// Scratch (device globals -- no allocation allowed)
__device__ float g_xa[M_SEQ*EE];
__device__ float g_xb[M_SEQ*HH];
__device__ float g_xg[M_SEQ*G4];
__device__ float g_encp[NB*TI*JJ];
__device__ float g_decp[M_SEQ*JJ];
__device__ float g_h[3][2][NB*HH];   // [layer][tick parity][b*H+j]
__device__ unsigned g_bar;           // global barrier arrival counter

// ---------------------------------------------------------------------------
// Embedding with prepended blank token
// ---------------------------------------------------------------------------
__global__ void k_embed(const int* __restrict__ tgt, const float* __restrict__ emb,
                        float* __restrict__ x) {
    int idx = blockIdx.x*blockDim.x + threadIdx.x;
    if (idx >= M_SEQ*EE) return;
    int e = idx & (EE-1);
    int m = idx >> 9;                  // EE = 512
    int n = m / TO1, t = m - n*TO1;
    int tok = (t == 0) ? 0 : tgt[n*TO + t - 1];
    x[idx] = emb[tok*EE + e];
}

__global__ void k_reset() {
    if (threadIdx.x == 0) g_bar = 0u;
}

// ---------------------------------------------------------------------------
// Generic C[m,n] = sum_k A[m,k]*B[n,k] + b1[n] + b2[n]
// 64x64x16 tiles, 256 threads, 4x4 microtile. N,K multiples of 64/16; M guarded.
// ---------------------------------------------------------------------------
__global__ void k_gemm_abT(const float* __restrict__ A, const float* __restrict__ B,
                           const float* __restrict__ b1, const float* __restrict__ b2,
                           float* __restrict__ C, int M, int Nn, int K) {
    __shared__ float As[16][64];
    __shared__ float Bs[16][64];
    const int tid = threadIdx.x;
    const int m0 = blockIdx.x*64, n0 = blockIdx.y*64;
    const int lr = tid >> 2;            // 0..63
    const int lk = (tid & 3) << 2;      // 0,4,8,12
    const int tx = tid & 15, ty = tid >> 4;
    float acc[4][4] = {};
    const bool mval = (m0 + lr) < M;
    const float* Ap = A + (size_t)(m0+lr)*K + lk;
    const float* Bp = B + (size_t)(n0+lr)*K + lk;

    for (int k0 = 0; k0 < K; k0 += 16) {
        float4 av = make_float4(0.f,0.f,0.f,0.f);
        if (mval) av = *(const float4*)(Ap + k0);
        float4 bv = *(const float4*)(Bp + k0);
        As[lk+0][lr]=av.x; As[lk+1][lr]=av.y; As[lk+2][lr]=av.z; As[lk+3][lr]=av.w;
        Bs[lk+0][lr]=bv.x; Bs[lk+1][lr]=bv.y; Bs[lk+2][lr]=bv.z; Bs[lk+3][lr]=bv.w;
        __syncthreads();
#pragma unroll
        for (int k = 0; k < 16; k++) {
            float4 a4 = *(const float4*)&As[k][ty*4];
            float4 b4 = *(const float4*)&Bs[k][tx*4];
            float aa[4] = {a4.x,a4.y,a4.z,a4.w};
            float bb[4] = {b4.x,b4.y,b4.z,b4.w};
#pragma unroll
            for (int i=0;i<4;i++)
#pragma unroll
                for (int j=0;j<4;j++) acc[i][j] += aa[i]*bb[j];
        }
        __syncthreads();
    }
    float bias[4];
#pragma unroll
    for (int j=0;j<4;j++) {
        int nn = n0 + tx*4 + j;
        bias[j] = (b1 ? b1[nn] : 0.f) + (b2 ? b2[nn] : 0.f);
    }
#pragma unroll
    for (int i=0;i<4;i++) {
        int m = m0 + ty*4 + i;
        if (m < M) {
            float4 o = make_float4(acc[i][0]+bias[0], acc[i][1]+bias[1],
                                   acc[i][2]+bias[2], acc[i][3]+bias[3]);
            *(float4*)&C[(size_t)m*Nn + n0 + tx*4] = o;
        }
    }
}

// ---------------------------------------------------------------------------
// Persistent wavefront LSTM: one launch for all 3 layers x 65 steps.
// Block bx: layer = bx>>5, 16 hidden units (j0 = (bx&31)*16) x 4 gates x 4 batches.
// Tick T runs layer l at t = T-l. Global spin barrier between ticks.
// ---------------------------------------------------------------------------
__device__ __forceinline__ float sigf(float x) { return 1.f/(1.f + expf(-x)); }

__device__ __forceinline__ void dot_acc(const float* __restrict__ W, int row,
                                        const float* sh, int lane,
                                        float& a0, float& a1, float& a2, float& a3) {
    const float4* wp = (const float4*)(W + (size_t)row*HH);
#pragma unroll
    for (int it = 0; it < 4; it++) {
        int kv = it*32 + lane;
        float4 w  = wp[kv];
        float4 h0 = *(const float4*)&sh[0*HH + kv*4];
        float4 h1 = *(const float4*)&sh[1*HH + kv*4];
        float4 h2 = *(const float4*)&sh[2*HH + kv*4];
        float4 h3 = *(const float4*)&sh[3*HH + kv*4];
        a0 += w.x*h0.x + w.y*h0.y + w.z*h0.z + w.w*h0.w;
        a1 += w.x*h1.x + w.y*h1.y + w.z*h1.z + w.w*h1.w;
        a2 += w.x*h2.x + w.y*h2.y + w.z*h2.z + w.w*h2.w;
        a3 += w.x*h3.x + w.y*h3.y + w.z*h3.z + w.w*h3.w;
    }
}

__global__ void __launch_bounds__(256, 1) k_lstm_wave(
    const float* __restrict__ xg0,
    const float* __restrict__ Whh0,
    const float* __restrict__ Wih1, const float* __restrict__ Whh1,
    const float* __restrict__ bih1, const float* __restrict__ bhh1,
    const float* __restrict__ Wih2, const float* __restrict__ Whh2,
    const float* __restrict__ bih2, const float* __restrict__ bhh2,
    float* __restrict__ out_seq)
{
    const int layer = blockIdx.x >> 5;
    const int blk   = blockIdx.x & 31;
    const int j0    = blk * 16;
    const int tid   = threadIdx.x, warp = tid >> 5, lane = tid & 31;

    const float* Whh = (layer==0) ? Whh0 : (layer==1 ? Whh1 : Whh2);
    const float* Wih = (layer==1) ? Wih1 : Wih2;   // unused for layer 0
    const float* bi  = (layer==1) ? bih1 : bih2;
    const float* bh  = (layer==1) ? bhh1 : bhh2;

    __shared__ float sh[NB*HH];          // h_prev (own layer)
    __shared__ float si[NB*HH];          // h_in   (layer-1 output), layers 1,2
    __shared__ float gsm[4][NB][16];

    // Epilogue-thread persistent state: c in registers, biases hoisted.
    const int eb = tid >> 4, ejj = tid & 15, ej = j0 + ejj;
    float c_reg = 0.f;
    float bias_q[4] = {0.f, 0.f, 0.f, 0.f};
    if (tid < 64 && layer > 0) {
#pragma unroll
        for (int q = 0; q < 4; q++) bias_q[q] = bi[q*HH + ej] + bh[q*HH + ej];
    }

    volatile unsigned* barp = &g_bar;

    for (int tick = 0; tick < NTICK; tick++) {
        const int t = tick - layer;
        if (t >= 0 && t < TO1) {
            const int rp = (tick + 1) & 1;        // parity written at tick-1
            const bool havePrev = (t > 0);
            if (havePrev) {
                const float* hp = g_h[layer][rp];
                for (int i = tid; i < NB*HH; i += 256) sh[i] = __ldcg(hp + i);
            }
            if (layer > 0) {
                const float* hi = g_h[layer-1][rp];
                for (int i = tid; i < NB*HH; i += 256) si[i] = __ldcg(hi + i);
            }
            __syncthreads();
#pragma unroll
            for (int r = 0; r < 8; r++) {
                int rl = warp*8 + r;                 // 0..63
                int q = rl >> 4, jj = rl & 15;
                int row = q*HH + j0 + jj;
                float a0=0.f, a1=0.f, a2=0.f, a3=0.f;
                if (havePrev) dot_acc(Whh, row, sh, lane, a0, a1, a2, a3);
                if (layer > 0) dot_acc(Wih, row, si, lane, a0, a1, a2, a3);
#pragma unroll
                for (int off = 16; off; off >>= 1) {
                    a0 += __shfl_down_sync(0xffffffffu, a0, off);
                    a1 += __shfl_down_sync(0xffffffffu, a1, off);
                    a2 += __shfl_down_sync(0xffffffffu, a2, off);
                    a3 += __shfl_down_sync(0xffffffffu, a3, off);
                }
                if (lane == 0) {
                    gsm[q][0][jj]=a0; gsm[q][1][jj]=a1; gsm[q][2][jj]=a2; gsm[q][3][jj]=a3;
                }
            }
            __syncthreads();
            if (tid < 64) {
                float p[4];
                if (layer == 0) {
                    const float* xp = xg0 + (size_t)(eb*TO1 + t)*G4;
#pragma unroll
                    for (int q = 0; q < 4; q++) p[q] = gsm[q][eb][ejj] + xp[q*HH + ej];
                } else {
#pragma unroll
                    for (int q = 0; q < 4; q++) p[q] = gsm[q][eb][ejj] + bias_q[q];
                }
                float iv = sigf(p[0]), fv = sigf(p[1]), gv = tanhf(p[2]), ov = sigf(p[3]);
                c_reg = fv*c_reg + iv*gv;
                float h = ov * tanhf(c_reg);
                g_h[layer][tick & 1][eb*HH + ej] = h;
                if (layer == 2) out_seq[(size_t)(eb*TO1 + t)*HH + ej] = h;
                __threadfence();   // make h visible device-wide before arrival
            }
        }
        // ---- global barrier (all 96 blocks resident: grid <= SM count) ----
        __syncthreads();
        if (tid == 0) {
            atomicAdd(&g_bar, 1u);
            unsigned target = (unsigned)gridDim.x * (unsigned)(tick + 1);
            while (*barp < target) { }
        }
        __syncthreads();
    }
}

// ---------------------------------------------------------------------------
// Final fused kernel: out[m, v] = sum_j tanh(encp[n,t,j] + decp[n,u,j]) * outw[v,j]
// m = (n*TI + t)*TO1 + u.  128x128x8 tiles, 256 threads, 8x8 microtile.
// ---------------------------------------------------------------------------
__global__ void k_gemm_out(const float* __restrict__ encp, const float* __restrict__ decp,
                           const float* __restrict__ outw, float* __restrict__ out) {
    __shared__ float As[8][128];
    __shared__ float Bs[8][128];
    const int tid = threadIdx.x;
    const int m0 = blockIdx.x * 128;
    const int v0 = blockIdx.y * 128;
    const int lm = tid >> 1;             // 0..127
    const int lk = (tid & 1) << 2;       // 0 or 4
    const int m   = m0 + lm;
    const int n   = m / (TI*TO1);
    const int rem = m - n*(TI*TO1);
    const int t   = rem / TO1;
    const int u   = rem - t*TO1;
    const float* ep = encp + (size_t)(n*TI + t)*JJ + lk;
    const float* dp = decp + (size_t)(n*TO1 + u)*JJ + lk;
    const float* bp = outw + (size_t)(v0 + lm)*JJ + lk;
    const int tx = tid & 15, ty = tid >> 4;
    float acc[8][8] = {};

    for (int k0 = 0; k0 < JJ; k0 += 8) {
        float4 e4 = *(const float4*)(ep + k0);
        float4 d4 = *(const float4*)(dp + k0);
        As[lk+0][lm] = tanhf(e4.x + d4.x);
        As[lk+1][lm] = tanhf(e4.y + d4.y);
        As[lk+2][lm] = tanhf(e4.z + d4.z);
        As[lk+3][lm] = tanhf(e4.w + d4.w);
        float4 b4 = *(const float4*)(bp + k0);
        Bs[lk+0][lm] = b4.x; Bs[lk+1][lm] = b4.y; Bs[lk+2][lm] = b4.z; Bs[lk+3][lm] = b4.w;
        __syncthreads();
#pragma unroll
        for (int k = 0; k < 8; k++) {
            float a[8], b[8];
            *(float4*)&a[0] = *(const float4*)&As[k][ty*8];
            *(float4*)&a[4] = *(const float4*)&As[k][ty*8+4];
            *(float4*)&b[0] = *(const float4*)&Bs[k][tx*8];
            *(float4*)&b[4] = *(const float4*)&Bs[k][tx*8+4];
#pragma unroll
            for (int i=0;i<8;i++)
#pragma unroll
                for (int j=0;j<8;j++) acc[i][j] += a[i]*b[j];
        }
        __syncthreads();
    }
#pragma unroll
    for (int i=0;i<8;i++) {
        size_t mm = (size_t)(m0 + ty*8 + i);
        float* op = out + mm*VV + v0 + tx*8;
        *(float4*)(op)   = make_float4(acc[i][0],acc[i][1],acc[i][2],acc[i][3]);
        *(float4*)(op+4) = make_float4(acc[i][4],acc[i][5],acc[i][6],acc[i][7]);
    }
}

// ---------------------------------------------------------------------------
extern "C" void kernel_launch(void* const* d_in, const int* in_sizes, int n_in,
                              void* d_out, int out_size) {
    const float* enc_out = (const float*)d_in[0];
    const int*   tgt     = (const int*)  d_in[1];
    const float* emb     = (const float*)d_in[2];
    const float* Wih0    = (const float*)d_in[3];
    const float* Whh0    = (const float*)d_in[4];
    const float* bih0    = (const float*)d_in[5];
    const float* bhh0    = (const float*)d_in[6];
    const float* Wih1    = (const float*)d_in[7];
    const float* Whh1    = (const float*)d_in[8];
    const float* bih1    = (const float*)d_in[9];
    const float* bhh1    = (const float*)d_in[10];
    const float* Wih2    = (const float*)d_in[11];
    const float* Whh2    = (const float*)d_in[12];
    const float* bih2    = (const float*)d_in[13];
    const float* bhh2    = (const float*)d_in[14];
    const float* enc_w   = (const float*)d_in[15];
    const float* dec_w   = (const float*)d_in[16];
    const float* dec_b   = (const float*)d_in[17];
    const float* out_w   = (const float*)d_in[18];
    float* out = (float*)d_out;

    float *xa, *xb, *xg, *encp, *decp;
    cudaGetSymbolAddress((void**)&xa,   g_xa);
    cudaGetSymbolAddress((void**)&xb,   g_xb);
    cudaGetSymbolAddress((void**)&xg,   g_xg);
    cudaGetSymbolAddress((void**)&encp, g_encp);
    cudaGetSymbolAddress((void**)&decp, g_decp);

    // 1) embedding
    k_embed<<<(M_SEQ*EE + 255)/256, 256>>>(tgt, emb, xa);

    // 2) layer-0 input gates precompute: xg0 = x @ Wih0^T + bih0 + bhh0
    {
        dim3 g((M_SEQ + 63)/64, G4/64);
        k_gemm_abT<<<g, 256>>>(xa, Wih0, bih0, bhh0, xg, M_SEQ, G4, HH);
    }

    // 3) persistent wavefront LSTM (all 3 layers, 65 steps, one launch)
    k_reset<<<1, 32>>>();
    k_lstm_wave<<<GRID_LSTM, 256>>>(xg, Whh0,
                                    Wih1, Whh1, bih1, bhh1,
                                    Wih2, Whh2, bih2, bhh2, xb);

    // 4) enc_p, dec_p projections
    {
        dim3 g((NB*TI)/64, JJ/64);
        k_gemm_abT<<<g, 256>>>(enc_out, enc_w, nullptr, nullptr, encp, NB*TI, JJ, 512);
    }
    {
        dim3 g((M_SEQ + 63)/64, JJ/64);
        k_gemm_abT<<<g, 256>>>(xb, dec_w, dec_b, nullptr, decp, M_SEQ, JJ, HH);
    }

    // 5) fused tanh(joint) @ out_w^T
    {
        dim3 g(M_OUT/128, VV/128);
        k_gemm_out<<<g, 256>>>(encp, decp, out_w, out);
    }
}

// round 4
// speedup vs baseline: 2.5796x; 2.1337x over previous
#include <cuda_runtime.h>
#include <math.h>
#include <stdint.h>

#define NB  4
#define TI  512
#define TO  64
#define TO1 65
#define VV  1024
#define EE  512
#define HH  512
#define JJ  512
#define G4  2048                 // 4*H
#define M_SEQ (NB*TO1)           // 260
#define M_OUT (NB*TI*TO1)        // 133120
#define NTICK (TO1 + 2)          // wavefront depth: 67
#define GRID_LSTM 96             // 3 layers x 32 blocks; co-resident

// Scratch (device globals -- no allocation allowed)
__device__ float g_xa[M_SEQ*EE];
__device__ float g_xb[M_SEQ*HH];
__device__ float g_xg[M_SEQ*G4];
__device__ float g_encp[NB*TI*JJ];
__device__ float g_decp[M_SEQ*JJ];
__device__ float g_h[3][2][NB*HH];
__device__ unsigned g_bar;

// ---------------------------------------------------------------------------
__global__ void k_embed(const int* __restrict__ tgt, const float* __restrict__ emb,
                        float* __restrict__ x) {
    int idx = blockIdx.x*blockDim.x + threadIdx.x;
    if (idx >= M_SEQ*EE) return;
    int e = idx & (EE-1);
    int m = idx >> 9;
    int n = m / TO1, t = m - n*TO1;
    int tok = (t == 0) ? 0 : tgt[n*TO + t - 1];
    x[idx] = emb[tok*EE + e];
}

__global__ void k_reset() {
    if (threadIdx.x == 0) g_bar = 0u;
}

// ---------------------------------------------------------------------------
// C[m,n] = sum_k A[m,k]*B[n,k] + b1[n] + b2[n]   (small/medium GEMMs)
// ---------------------------------------------------------------------------
__global__ void k_gemm_abT(const float* __restrict__ A, const float* __restrict__ B,
                           const float* __restrict__ b1, const float* __restrict__ b2,
                           float* __restrict__ C, int M, int Nn, int K) {
    __shared__ float As[16][64];
    __shared__ float Bs[16][64];
    const int tid = threadIdx.x;
    const int m0 = blockIdx.x*64, n0 = blockIdx.y*64;
    const int lr = tid >> 2;
    const int lk = (tid & 3) << 2;
    const int tx = tid & 15, ty = tid >> 4;
    float acc[4][4] = {};
    const bool mval = (m0 + lr) < M;
    const float* Ap = A + (size_t)(m0+lr)*K + lk;
    const float* Bp = B + (size_t)(n0+lr)*K + lk;

    for (int k0 = 0; k0 < K; k0 += 16) {
        float4 av = make_float4(0.f,0.f,0.f,0.f);
        if (mval) av = *(const float4*)(Ap + k0);
        float4 bv = *(const float4*)(Bp + k0);
        As[lk+0][lr]=av.x; As[lk+1][lr]=av.y; As[lk+2][lr]=av.z; As[lk+3][lr]=av.w;
        Bs[lk+0][lr]=bv.x; Bs[lk+1][lr]=bv.y; Bs[lk+2][lr]=bv.z; Bs[lk+3][lr]=bv.w;
        __syncthreads();
#pragma unroll
        for (int k = 0; k < 16; k++) {
            float4 a4 = *(const float4*)&As[k][ty*4];
            float4 b4 = *(const float4*)&Bs[k][tx*4];
            float aa[4] = {a4.x,a4.y,a4.z,a4.w};
            float bb[4] = {b4.x,b4.y,b4.z,b4.w};
#pragma unroll
            for (int i=0;i<4;i++)
#pragma unroll
                for (int j=0;j<4;j++) acc[i][j] += aa[i]*bb[j];
        }
        __syncthreads();
    }
    float bias[4];
#pragma unroll
    for (int j=0;j<4;j++) {
        int nn = n0 + tx*4 + j;
        bias[j] = (b1 ? b1[nn] : 0.f) + (b2 ? b2[nn] : 0.f);
    }
#pragma unroll
    for (int i=0;i<4;i++) {
        int m = m0 + ty*4 + i;
        if (m < M) {
            float4 o = make_float4(acc[i][0]+bias[0], acc[i][1]+bias[1],
                                   acc[i][2]+bias[2], acc[i][3]+bias[3]);
            *(float4*)&C[(size_t)m*Nn + n0 + tx*4] = o;
        }
    }
}

// ---------------------------------------------------------------------------
// Persistent wavefront LSTM (unchanged)
// ---------------------------------------------------------------------------
__device__ __forceinline__ float sigf(float x) { return 1.f/(1.f + expf(-x)); }

__device__ __forceinline__ void dot_acc(const float* __restrict__ W, int row,
                                        const float* sh, int lane,
                                        float& a0, float& a1, float& a2, float& a3) {
    const float4* wp = (const float4*)(W + (size_t)row*HH);
#pragma unroll
    for (int it = 0; it < 4; it++) {
        int kv = it*32 + lane;
        float4 w  = wp[kv];
        float4 h0 = *(const float4*)&sh[0*HH + kv*4];
        float4 h1 = *(const float4*)&sh[1*HH + kv*4];
        float4 h2 = *(const float4*)&sh[2*HH + kv*4];
        float4 h3 = *(const float4*)&sh[3*HH + kv*4];
        a0 += w.x*h0.x + w.y*h0.y + w.z*h0.z + w.w*h0.w;
        a1 += w.x*h1.x + w.y*h1.y + w.z*h1.z + w.w*h1.w;
        a2 += w.x*h2.x + w.y*h2.y + w.z*h2.z + w.w*h2.w;
        a3 += w.x*h3.x + w.y*h3.y + w.z*h3.z + w.w*h3.w;
    }
}

__global__ void __launch_bounds__(256, 1) k_lstm_wave(
    const float* __restrict__ xg0,
    const float* __restrict__ Whh0,
    const float* __restrict__ Wih1, const float* __restrict__ Whh1,
    const float* __restrict__ bih1, const float* __restrict__ bhh1,
    const float* __restrict__ Wih2, const float* __restrict__ Whh2,
    const float* __restrict__ bih2, const float* __restrict__ bhh2,
    float* __restrict__ out_seq)
{
    const int layer = blockIdx.x >> 5;
    const int blk   = blockIdx.x & 31;
    const int j0    = blk * 16;
    const int tid   = threadIdx.x, warp = tid >> 5, lane = tid & 31;

    const float* Whh = (layer==0) ? Whh0 : (layer==1 ? Whh1 : Whh2);
    const float* Wih = (layer==1) ? Wih1 : Wih2;
    const float* bi  = (layer==1) ? bih1 : bih2;
    const float* bh  = (layer==1) ? bhh1 : bhh2;

    __shared__ float sh[NB*HH];
    __shared__ float si[NB*HH];
    __shared__ float gsm[4][NB][16];

    const int eb = tid >> 4, ejj = tid & 15, ej = j0 + ejj;
    float c_reg = 0.f;
    float bias_q[4] = {0.f, 0.f, 0.f, 0.f};
    if (tid < 64 && layer > 0) {
#pragma unroll
        for (int q = 0; q < 4; q++) bias_q[q] = bi[q*HH + ej] + bh[q*HH + ej];
    }

    volatile unsigned* barp = &g_bar;

    for (int tick = 0; tick < NTICK; tick++) {
        const int t = tick - layer;
        if (t >= 0 && t < TO1) {
            const int rp = (tick + 1) & 1;
            const bool havePrev = (t > 0);
            if (havePrev) {
                const float* hp = g_h[layer][rp];
                for (int i = tid; i < NB*HH; i += 256) sh[i] = __ldcg(hp + i);
            }
            if (layer > 0) {
                const float* hi = g_h[layer-1][rp];
                for (int i = tid; i < NB*HH; i += 256) si[i] = __ldcg(hi + i);
            }
            __syncthreads();
#pragma unroll
            for (int r = 0; r < 8; r++) {
                int rl = warp*8 + r;
                int q = rl >> 4, jj = rl & 15;
                int row = q*HH + j0 + jj;
                float a0=0.f, a1=0.f, a2=0.f, a3=0.f;
                if (havePrev) dot_acc(Whh, row, sh, lane, a0, a1, a2, a3);
                if (layer > 0) dot_acc(Wih, row, si, lane, a0, a1, a2, a3);
#pragma unroll
                for (int off = 16; off; off >>= 1) {
                    a0 += __shfl_down_sync(0xffffffffu, a0, off);
                    a1 += __shfl_down_sync(0xffffffffu, a1, off);
                    a2 += __shfl_down_sync(0xffffffffu, a2, off);
                    a3 += __shfl_down_sync(0xffffffffu, a3, off);
                }
                if (lane == 0) {
                    gsm[q][0][jj]=a0; gsm[q][1][jj]=a1; gsm[q][2][jj]=a2; gsm[q][3][jj]=a3;
                }
            }
            __syncthreads();
            if (tid < 64) {
                float p[4];
                if (layer == 0) {
                    const float* xp = xg0 + (size_t)(eb*TO1 + t)*G4;
#pragma unroll
                    for (int q = 0; q < 4; q++) p[q] = gsm[q][eb][ejj] + xp[q*HH + ej];
                } else {
#pragma unroll
                    for (int q = 0; q < 4; q++) p[q] = gsm[q][eb][ejj] + bias_q[q];
                }
                float iv = sigf(p[0]), fv = sigf(p[1]), gv = tanhf(p[2]), ov = sigf(p[3]);
                c_reg = fv*c_reg + iv*gv;
                float h = ov * tanhf(c_reg);
                g_h[layer][tick & 1][eb*HH + ej] = h;
                if (layer == 2) out_seq[(size_t)(eb*TO1 + t)*HH + ej] = h;
                __threadfence();
            }
        }
        __syncthreads();
        if (tid == 0) {
            atomicAdd(&g_bar, 1u);
            unsigned target = (unsigned)gridDim.x * (unsigned)(tick + 1);
            while (*barp < target) { }
        }
        __syncthreads();
    }
}

// ---------------------------------------------------------------------------
// Fused output GEMM on tensor cores via mma.sync (tf32, base sm_103 target):
//   out[m, v] = sum_j tanh(encp[n,t,j] + decp[n,u,j]) * outw[v,j]
// CTA tile 128x128, K chunks of 32. 8 warps = 2(M) x 4(N); warp tile 64x32.
// SMEM pitch 36 floats -> conflict-free fragment loads.
// ---------------------------------------------------------------------------
#define PITCH 36

__device__ __forceinline__ uint32_t to_tf32(float x) {
    uint32_t y;
    asm("cvt.rna.tf32.f32 %0, %1;" : "=r"(y) : "f"(x));
    return y;
}

__device__ __forceinline__ void mma_tf32(float d[4], uint32_t a0, uint32_t a1,
                                         uint32_t a2, uint32_t a3,
                                         uint32_t b0, uint32_t b1) {
    asm volatile(
        "mma.sync.aligned.m16n8k8.row.col.f32.tf32.tf32.f32 "
        "{%0,%1,%2,%3}, {%4,%5,%6,%7}, {%8,%9}, {%0,%1,%2,%3};"
        : "+f"(d[0]), "+f"(d[1]), "+f"(d[2]), "+f"(d[3])
        : "r"(a0), "r"(a1), "r"(a2), "r"(a3), "r"(b0), "r"(b1));
}

__global__ void __launch_bounds__(256, 2) k_mma_out(
    const float* __restrict__ encp, const float* __restrict__ decp,
    const float* __restrict__ outw, float* __restrict__ out)
{
    __shared__ uint32_t As[128*PITCH];
    __shared__ uint32_t Bs[128*PITCH];

    const int tid = threadIdx.x;
    const int m0  = blockIdx.x * 128;
    const int v0  = blockIdx.y * 128;

    // --- fill addressing: 2 threads per row, 16 cols each ---
    const int fr = tid >> 1;             // 0..127
    const int fc = (tid & 1) * 16;       // 0 or 16
    const int m   = m0 + fr;
    const int n   = m / (TI*TO1);
    const int rem = m - n*(TI*TO1);
    const int t   = rem / TO1;
    const int u   = rem - t*TO1;
    const float* ep = encp + (size_t)(n*TI + t)*JJ + fc;
    const float* dp = decp + (size_t)(n*TO1 + u)*JJ + fc;
    const float* bp = outw + (size_t)(v0 + fr)*JJ + fc;
    uint32_t* Aw = &As[fr*PITCH + fc];
    uint32_t* Bw = &Bs[fr*PITCH + fc];

    // --- warp/fragment addressing ---
    const int w = tid >> 5, lane = tid & 31;
    const int wm = w >> 2, wn = w & 3;         // 2 x 4 warp grid
    const int g = lane >> 2, tg = lane & 3;

    float d[4][4][4];
#pragma unroll
    for (int i = 0; i < 4; i++)
#pragma unroll
        for (int j = 0; j < 4; j++)
#pragma unroll
            for (int q = 0; q < 4; q++) d[i][j][q] = 0.f;

    const uint32_t* Afrag = &As[(wm*64 + g)*PITCH + tg];
    const uint32_t* Bfrag = &Bs[(wn*32 + g)*PITCH + tg];

    for (int c = 0; c < 16; c++) {
        const int k0 = c * 32;
        __syncthreads();
        // A fill: tanh(enc+dec) -> tf32
#pragma unroll
        for (int i = 0; i < 4; i++) {
            float4 e4 = *(const float4*)(ep + k0 + i*4);
            float4 d4 = *(const float4*)(dp + k0 + i*4);
            uint4 a4;
            a4.x = to_tf32(tanhf(e4.x + d4.x));
            a4.y = to_tf32(tanhf(e4.y + d4.y));
            a4.z = to_tf32(tanhf(e4.z + d4.z));
            a4.w = to_tf32(tanhf(e4.w + d4.w));
            *(uint4*)(Aw + i*4) = a4;
        }
        // B fill: out_w rows -> tf32
#pragma unroll
        for (int i = 0; i < 4; i++) {
            float4 b4 = *(const float4*)(bp + k0 + i*4);
            uint4 q4;
            q4.x = to_tf32(b4.x); q4.y = to_tf32(b4.y);
            q4.z = to_tf32(b4.z); q4.w = to_tf32(b4.w);
            *(uint4*)(Bw + i*4) = q4;
        }
        __syncthreads();

#pragma unroll
        for (int ks = 0; ks < 4; ks++) {
            const int k = ks * 8;
            uint32_t af[4][4];
#pragma unroll
            for (int mt = 0; mt < 4; mt++) {
                const uint32_t* ap = Afrag + mt*16*PITCH + k;
                af[mt][0] = ap[0];
                af[mt][1] = ap[8*PITCH];
                af[mt][2] = ap[4];
                af[mt][3] = ap[8*PITCH + 4];
            }
            uint32_t bf[4][2];
#pragma unroll
            for (int nt = 0; nt < 4; nt++) {
                const uint32_t* bq = Bfrag + nt*8*PITCH + k;
                bf[nt][0] = bq[0];
                bf[nt][1] = bq[4];
            }
#pragma unroll
            for (int mt = 0; mt < 4; mt++)
#pragma unroll
                for (int nt = 0; nt < 4; nt++)
                    mma_tf32(d[mt][nt], af[mt][0], af[mt][1], af[mt][2], af[mt][3],
                             bf[nt][0], bf[nt][1]);
        }
    }

    // --- epilogue: c0/c1 at (row g, cols 2tg,2tg+1), c2/c3 at row g+8 ---
#pragma unroll
    for (int mt = 0; mt < 4; mt++) {
        const int row = m0 + wm*64 + mt*16 + g;
#pragma unroll
        for (int nt = 0; nt < 4; nt++) {
            const int col = v0 + wn*32 + nt*8 + 2*tg;
            *(float2*)(out + (size_t)row*VV + col) =
                make_float2(d[mt][nt][0], d[mt][nt][1]);
            *(float2*)(out + (size_t)(row+8)*VV + col) =
                make_float2(d[mt][nt][2], d[mt][nt][3]);
        }
    }
}

// ---------------------------------------------------------------------------
extern "C" void kernel_launch(void* const* d_in, const int* in_sizes, int n_in,
                              void* d_out, int out_size) {
    const float* enc_out = (const float*)d_in[0];
    const int*   tgt     = (const int*)  d_in[1];
    const float* emb     = (const float*)d_in[2];
    const float* Wih0    = (const float*)d_in[3];
    const float* Whh0    = (const float*)d_in[4];
    const float* bih0    = (const float*)d_in[5];
    const float* bhh0    = (const float*)d_in[6];
    const float* Wih1    = (const float*)d_in[7];
    const float* Whh1    = (const float*)d_in[8];
    const float* bih1    = (const float*)d_in[9];
    const float* bhh1    = (const float*)d_in[10];
    const float* Wih2    = (const float*)d_in[11];
    const float* Whh2    = (const float*)d_in[12];
    const float* bih2    = (const float*)d_in[13];
    const float* bhh2    = (const float*)d_in[14];
    const float* enc_w   = (const float*)d_in[15];
    const float* dec_w   = (const float*)d_in[16];
    const float* dec_b   = (const float*)d_in[17];
    const float* out_w   = (const float*)d_in[18];
    float* out = (float*)d_out;

    float *xa, *xb, *xg, *encp, *decp;
    cudaGetSymbolAddress((void**)&xa,   g_xa);
    cudaGetSymbolAddress((void**)&xb,   g_xb);
    cudaGetSymbolAddress((void**)&xg,   g_xg);
    cudaGetSymbolAddress((void**)&encp, g_encp);
    cudaGetSymbolAddress((void**)&decp, g_decp);

    // 1) embedding
    k_embed<<<(M_SEQ*EE + 255)/256, 256>>>(tgt, emb, xa);

    // 2) layer-0 input gates precompute
    {
        dim3 g((M_SEQ + 63)/64, G4/64);
        k_gemm_abT<<<g, 256>>>(xa, Wih0, bih0, bhh0, xg, M_SEQ, G4, HH);
    }

    // 3) persistent wavefront LSTM
    k_reset<<<1, 32>>>();
    k_lstm_wave<<<GRID_LSTM, 256>>>(xg, Whh0,
                                    Wih1, Whh1, bih1, bhh1,
                                    Wih2, Whh2, bih2, bhh2, xb);

    // 4) enc_p, dec_p projections
    {
        dim3 g((NB*TI)/64, JJ/64);
        k_gemm_abT<<<g, 256>>>(enc_out, enc_w, nullptr, nullptr, encp, NB*TI, JJ, 512);
    }
    {
        dim3 g((M_SEQ + 63)/64, JJ/64);
        k_gemm_abT<<<g, 256>>>(xb, dec_w, dec_b, nullptr, decp, M_SEQ, JJ, HH);
    }

    // 5) fused tanh(joint) @ out_w^T on tensor cores (mma.sync tf32)
    {
        dim3 g(M_OUT/128, VV/128);
        k_mma_out<<<g, 256>>>(encp, decp, out_w, out);
    }
}

// round 5
// speedup vs baseline: 3.5403x; 1.3725x over previous
#include <cuda_runtime.h>
#include <cuda_fp16.h>
#include <math.h>
#include <stdint.h>

#define NB  4
#define TI  512
#define TO  64
#define TO1 65
#define VV  1024
#define EE  512
#define HH  512
#define JJ  512
#define G4  2048
#define M_SEQ (NB*TO1)           // 260
#define M_OUT (NB*TI*TO1)        // 133120
#define NTICK (TO1 + 2)
#define GRID_LSTM 96

// Scratch (device globals -- no allocation allowed)
__device__ float g_xa[M_SEQ*EE];
__device__ float g_xb[M_SEQ*HH];
__device__ float g_xg[M_SEQ*G4];
__device__ float g_encp[NB*TI*JJ];
__device__ float g_decp[M_SEQ*JJ];
__device__ float g_h[3][2][NB*HH];
__device__ unsigned g_bar;
__device__ unsigned g_T[M_OUT*256];    // fp16 tanh(enc+dec), packed pairs (136 MB)
__device__ unsigned g_bw[VV*256];      // fp16 out_w, packed pairs (1 MB)

// ---------------------------------------------------------------------------
__global__ void k_embed(const int* __restrict__ tgt, const float* __restrict__ emb,
                        float* __restrict__ x) {
    int idx = blockIdx.x*blockDim.x + threadIdx.x;
    if (idx >= M_SEQ*EE) return;
    int e = idx & (EE-1);
    int m = idx >> 9;
    int n = m / TO1, t = m - n*TO1;
    int tok = (t == 0) ? 0 : tgt[n*TO + t - 1];
    x[idx] = emb[tok*EE + e];
}

__global__ void k_reset() {
    if (threadIdx.x == 0) g_bar = 0u;
}

// ---------------------------------------------------------------------------
// C[m,n] = sum_k A[m,k]*B[n,k] + b1[n] + b2[n]   (small/medium GEMMs)
// ---------------------------------------------------------------------------
__global__ void k_gemm_abT(const float* __restrict__ A, const float* __restrict__ B,
                           const float* __restrict__ b1, const float* __restrict__ b2,
                           float* __restrict__ C, int M, int Nn, int K) {
    __shared__ float As[16][64];
    __shared__ float Bs[16][64];
    const int tid = threadIdx.x;
    const int m0 = blockIdx.x*64, n0 = blockIdx.y*64;
    const int lr = tid >> 2;
    const int lk = (tid & 3) << 2;
    const int tx = tid & 15, ty = tid >> 4;
    float acc[4][4] = {};
    const bool mval = (m0 + lr) < M;
    const float* Ap = A + (size_t)(m0+lr)*K + lk;
    const float* Bp = B + (size_t)(n0+lr)*K + lk;

    for (int k0 = 0; k0 < K; k0 += 16) {
        float4 av = make_float4(0.f,0.f,0.f,0.f);
        if (mval) av = *(const float4*)(Ap + k0);
        float4 bv = *(const float4*)(Bp + k0);
        As[lk+0][lr]=av.x; As[lk+1][lr]=av.y; As[lk+2][lr]=av.z; As[lk+3][lr]=av.w;
        Bs[lk+0][lr]=bv.x; Bs[lk+1][lr]=bv.y; Bs[lk+2][lr]=bv.z; Bs[lk+3][lr]=bv.w;
        __syncthreads();
#pragma unroll
        for (int k = 0; k < 16; k++) {
            float4 a4 = *(const float4*)&As[k][ty*4];
            float4 b4 = *(const float4*)&Bs[k][tx*4];
            float aa[4] = {a4.x,a4.y,a4.z,a4.w};
            float bb[4] = {b4.x,b4.y,b4.z,b4.w};
#pragma unroll
            for (int i=0;i<4;i++)
#pragma unroll
                for (int j=0;j<4;j++) acc[i][j] += aa[i]*bb[j];
        }
        __syncthreads();
    }
    float bias[4];
#pragma unroll
    for (int j=0;j<4;j++) {
        int nn = n0 + tx*4 + j;
        bias[j] = (b1 ? b1[nn] : 0.f) + (b2 ? b2[nn] : 0.f);
    }
#pragma unroll
    for (int i=0;i<4;i++) {
        int m = m0 + ty*4 + i;
        if (m < M) {
            float4 o = make_float4(acc[i][0]+bias[0], acc[i][1]+bias[1],
                                   acc[i][2]+bias[2], acc[i][3]+bias[3]);
            *(float4*)&C[(size_t)m*Nn + n0 + tx*4] = o;
        }
    }
}

// ---------------------------------------------------------------------------
// Persistent wavefront LSTM: register-blocked rows (8 rows/warp share one
// streamed h read) -> 8x less SMEM crossbar traffic than round-2 version.
// ---------------------------------------------------------------------------
__device__ __forceinline__ float sigf(float x) { return 1.f/(1.f + expf(-x)); }

__device__ __forceinline__ void dot8(const float* __restrict__ Wrow0,
                                     const float* sh, int lane, float acc[8][4]) {
#pragma unroll
    for (int it = 0; it < 4; it++) {
        const int kv4 = (it*32 + lane) * 4;
        float4 h0 = *(const float4*)&sh[0*HH + kv4];
        float4 h1 = *(const float4*)&sh[1*HH + kv4];
        float4 h2 = *(const float4*)&sh[2*HH + kv4];
        float4 h3 = *(const float4*)&sh[3*HH + kv4];
#pragma unroll
        for (int r = 0; r < 8; r++) {
            float4 w = *(const float4*)(Wrow0 + (size_t)r*HH + kv4);
            acc[r][0] += w.x*h0.x + w.y*h0.y + w.z*h0.z + w.w*h0.w;
            acc[r][1] += w.x*h1.x + w.y*h1.y + w.z*h1.z + w.w*h1.w;
            acc[r][2] += w.x*h2.x + w.y*h2.y + w.z*h2.z + w.w*h2.w;
            acc[r][3] += w.x*h3.x + w.y*h3.y + w.z*h3.z + w.w*h3.w;
        }
    }
}

__global__ void __launch_bounds__(256, 1) k_lstm_wave(
    const float* __restrict__ xg0,
    const float* __restrict__ Whh0,
    const float* __restrict__ Wih1, const float* __restrict__ Whh1,
    const float* __restrict__ bih1, const float* __restrict__ bhh1,
    const float* __restrict__ Wih2, const float* __restrict__ Whh2,
    const float* __restrict__ bih2, const float* __restrict__ bhh2,
    float* __restrict__ out_seq)
{
    const int layer = blockIdx.x >> 5;
    const int blk   = blockIdx.x & 31;
    const int j0    = blk * 16;
    const int tid   = threadIdx.x, warp = tid >> 5, lane = tid & 31;

    const float* Whh = (layer==0) ? Whh0 : (layer==1 ? Whh1 : Whh2);
    const float* Wih = (layer==1) ? Wih1 : Wih2;
    const float* bi  = (layer==1) ? bih1 : bih2;
    const float* bh  = (layer==1) ? bhh1 : bhh2;

    __shared__ float sh[NB*HH];
    __shared__ float si[NB*HH];
    __shared__ float gsm[4][NB][16];

    // per-warp row block: 8 contiguous rows, same gate q
    const int rl0 = warp*8;
    const int q   = rl0 >> 4;
    const int jb  = rl0 & 15;
    const float* WhhR = Whh + (size_t)(q*HH + j0 + jb)*HH;
    const float* WihR = Wih + (size_t)(q*HH + j0 + jb)*HH;

    const int eb = tid >> 4, ejj = tid & 15, ej = j0 + ejj;
    float c_reg = 0.f;
    float bias_q[4] = {0.f, 0.f, 0.f, 0.f};
    if (tid < 64 && layer > 0) {
#pragma unroll
        for (int qq = 0; qq < 4; qq++) bias_q[qq] = bi[qq*HH + ej] + bh[qq*HH + ej];
    }

    volatile unsigned* barp = &g_bar;

    for (int tick = 0; tick < NTICK; tick++) {
        const int t = tick - layer;
        if (t >= 0 && t < TO1) {
            const int rp = (tick + 1) & 1;
            const bool havePrev = (t > 0);
            if (havePrev) {
                const float* hp = g_h[layer][rp];
                for (int i = tid; i < NB*HH; i += 256) sh[i] = __ldcg(hp + i);
            }
            if (layer > 0) {
                const float* hi = g_h[layer-1][rp];
                for (int i = tid; i < NB*HH; i += 256) si[i] = __ldcg(hi + i);
            }
            __syncthreads();

            float acc[8][4] = {};
            if (havePrev) dot8(WhhR, sh, lane, acc);
            if (layer > 0) dot8(WihR, si, lane, acc);
#pragma unroll
            for (int r = 0; r < 8; r++) {
#pragma unroll
                for (int off = 16; off; off >>= 1) {
                    acc[r][0] += __shfl_down_sync(0xffffffffu, acc[r][0], off);
                    acc[r][1] += __shfl_down_sync(0xffffffffu, acc[r][1], off);
                    acc[r][2] += __shfl_down_sync(0xffffffffu, acc[r][2], off);
                    acc[r][3] += __shfl_down_sync(0xffffffffu, acc[r][3], off);
                }
            }
            if (lane == 0) {
#pragma unroll
                for (int r = 0; r < 8; r++) {
                    gsm[q][0][jb+r] = acc[r][0];
                    gsm[q][1][jb+r] = acc[r][1];
                    gsm[q][2][jb+r] = acc[r][2];
                    gsm[q][3][jb+r] = acc[r][3];
                }
            }
            __syncthreads();
            if (tid < 64) {
                float p[4];
                if (layer == 0) {
                    const float* xp = xg0 + (size_t)(eb*TO1 + t)*G4;
#pragma unroll
                    for (int qq = 0; qq < 4; qq++) p[qq] = gsm[qq][eb][ejj] + xp[qq*HH + ej];
                } else {
#pragma unroll
                    for (int qq = 0; qq < 4; qq++) p[qq] = gsm[qq][eb][ejj] + bias_q[qq];
                }
                float iv = sigf(p[0]), fv = sigf(p[1]), gv = tanhf(p[2]), ov = sigf(p[3]);
                c_reg = fv*c_reg + iv*gv;
                float h = ov * tanhf(c_reg);
                g_h[layer][tick & 1][eb*HH + ej] = h;
                if (layer == 2) out_seq[(size_t)(eb*TO1 + t)*HH + ej] = h;
                __threadfence();
            }
        }
        __syncthreads();
        if (tid == 0) {
            atomicAdd(&g_bar, 1u);
            unsigned target = (unsigned)gridDim.x * (unsigned)(tick + 1);
            while (*barp < target) { }
        }
        __syncthreads();
    }
}

// ---------------------------------------------------------------------------
// T = fp16(tanh(encp + decp)), packed as u32 pairs: T[m*256 + j/2]
// ---------------------------------------------------------------------------
__global__ void k_tanh(const float* __restrict__ encp, const float* __restrict__ decp,
                       unsigned* __restrict__ T) {
    const int idx = blockIdx.x*256 + threadIdx.x;   // one per 8 floats
    const int m  = idx >> 6;
    const int jo = (idx & 63) << 3;
    const int n   = m / (TI*TO1);
    const int rem = m - n*(TI*TO1);
    const int t   = rem / TO1;
    const int u   = rem - t*TO1;
    const float* ep = encp + (size_t)(n*TI + t)*JJ + jo;
    const float* dp = decp + (size_t)(n*TO1 + u)*JJ + jo;
    float4 e0 = *(const float4*)ep, e1 = *(const float4*)(ep+4);
    float4 d0 = *(const float4*)dp, d1 = *(const float4*)(dp+4);
    __half2 h0 = __floats2half2_rn(tanhf(e0.x+d0.x), tanhf(e0.y+d0.y));
    __half2 h1 = __floats2half2_rn(tanhf(e0.z+d0.z), tanhf(e0.w+d0.w));
    __half2 h2 = __floats2half2_rn(tanhf(e1.x+d1.x), tanhf(e1.y+d1.y));
    __half2 h3 = __floats2half2_rn(tanhf(e1.z+d1.z), tanhf(e1.w+d1.w));
    uint4 o;
    o.x = *(unsigned*)&h0; o.y = *(unsigned*)&h1;
    o.z = *(unsigned*)&h2; o.w = *(unsigned*)&h3;
    *(uint4*)&T[(size_t)m*256 + (jo>>1)] = o;
}

// out_w fp32 -> fp16 pairs
__global__ void k_cvtB(const float* __restrict__ w, unsigned* __restrict__ o) {
    const int idx = blockIdx.x*256 + threadIdx.x;   // per 8 floats
    const float* s = w + (size_t)idx*8;
    float4 f0 = *(const float4*)s, f1 = *(const float4*)(s+4);
    __half2 h0 = __floats2half2_rn(f0.x, f0.y);
    __half2 h1 = __floats2half2_rn(f0.z, f0.w);
    __half2 h2 = __floats2half2_rn(f1.x, f1.y);
    __half2 h3 = __floats2half2_rn(f1.z, f1.w);
    uint4 v;
    v.x = *(unsigned*)&h0; v.y = *(unsigned*)&h1;
    v.z = *(unsigned*)&h2; v.w = *(unsigned*)&h3;
    *(uint4*)&o[(size_t)idx*4] = v;
}

// ---------------------------------------------------------------------------
// fp16 HMMA GEMM: out[m,v] = sum_j T[m,j] * out_w16[v,j]
// CTA 128(M) x 256(N); 8 warps 2x4, warp tile 64x64; K chunks of 64 (4 x k16);
// double-buffered fragment-packed SMEM.
// ---------------------------------------------------------------------------
#define NCH 8
#define APL 1056                 // A plane stride (u32): 32 blks * 33
#define BPL 4224                 // B plane stride (u32): 128 blks * 33
#define STG (4*APL + 2*BPL)      // 12672 u32 per stage
#define SMEM_MMA (2*STG*4)       // 101376 bytes

__device__ __forceinline__ void mma16816(float d[4], const unsigned a[4],
                                         const unsigned b[2]) {
    asm volatile(
        "mma.sync.aligned.m16n8k16.row.col.f32.f16.f16.f32 "
        "{%0,%1,%2,%3}, {%4,%5,%6,%7}, {%8,%9}, {%0,%1,%2,%3};"
        : "+f"(d[0]), "+f"(d[1]), "+f"(d[2]), "+f"(d[3])
        : "r"(a[0]), "r"(a[1]), "r"(a[2]), "r"(a[3]), "r"(b[0]), "r"(b[1]));
}

__global__ void __launch_bounds__(256) k_mma_out(
    const unsigned* __restrict__ T, const unsigned* __restrict__ Bw,
    float* __restrict__ out)
{
    extern __shared__ unsigned sm[];
    const int tid = threadIdx.x;
    const int m0 = blockIdx.x * 128;
    const int v0 = blockIdx.y * 256;

    // --- fill indexing ---
    const int fr = tid >> 1, fp = (tid & 1) * 16;          // A: 2 thr/row
    const unsigned* Trow = T + (size_t)(m0 + fr)*256 + fp;
    const int fwm = fr >> 6, fmt = (fr >> 4) & 3, fhi = (fr >> 3) & 1, fg = fr & 7;
    const unsigned* Brow = Bw + (size_t)(v0 + tid)*256;    // B: 1 thr/row
    const int bwn = tid >> 6, bnt = (tid >> 3) & 7, bg = tid & 7;

    auto fill = [&](int s, int c) {
        uint4 va[4];
#pragma unroll
        for (int j = 0; j < 4; j++) va[j] = *(const uint4*)(Trow + c*32 + j*4);
        uint4 vb[8];
#pragma unroll
        for (int j = 0; j < 8; j++) vb[j] = *(const uint4*)(Brow + c*32 + j*4);
        unsigned* ab = sm + s*STG;
        const unsigned* vau = (const unsigned*)va;
#pragma unroll
        for (int i = 0; i < 16; i++) {
            const int p = fp + i;
            const int ks = p >> 3, tg = p & 3, half = (p >> 2) & 1;
            const int reg = fhi + 2*half;
            const int blk = (fwm*4 + fmt)*4 + ks;
            ab[reg*APL + blk*33 + fg*4 + tg] = vau[i];
        }
        unsigned* bb = sm + s*STG + 4*APL;
        const unsigned* vbu = (const unsigned*)vb;
#pragma unroll
        for (int p = 0; p < 32; p++) {
            const int ks = p >> 3, tg = p & 3, half = (p >> 2) & 1;
            const int blk = (bwn*8 + bnt)*4 + ks;
            bb[half*BPL + blk*33 + bg*4 + tg] = vbu[p];
        }
    };

    // --- compute indexing ---
    const int w = tid >> 5, lane = tid & 31;
    const int wm = w >> 2, wn = w & 3;
    float d[4][8][4];
#pragma unroll
    for (int i = 0; i < 4; i++)
#pragma unroll
        for (int j = 0; j < 8; j++)
#pragma unroll
            for (int k = 0; k < 4; k++) d[i][j][k] = 0.f;

    fill(0, 0);
    for (int c = 0; c < NCH; c++) {
        __syncthreads();
        if (c + 1 < NCH) fill((c + 1) & 1, c + 1);
        const unsigned* ab = sm + (c & 1)*STG;
        const unsigned* bb = ab + 4*APL;
#pragma unroll
        for (int ks = 0; ks < 4; ks++) {
            unsigned a[4][4];
#pragma unroll
            for (int mt = 0; mt < 4; mt++) {
                const int off = ((wm*4 + mt)*4 + ks)*33 + lane;
                a[mt][0] = ab[off];
                a[mt][1] = ab[APL + off];
                a[mt][2] = ab[2*APL + off];
                a[mt][3] = ab[3*APL + off];
            }
            unsigned b[8][2];
#pragma unroll
            for (int nt = 0; nt < 8; nt++) {
                const int off = ((wn*8 + nt)*4 + ks)*33 + lane;
                b[nt][0] = bb[off];
                b[nt][1] = bb[BPL + off];
            }
#pragma unroll
            for (int mt = 0; mt < 4; mt++)
#pragma unroll
                for (int nt = 0; nt < 8; nt++)
                    mma16816(d[mt][nt], a[mt], b[nt]);
        }
    }

    // --- epilogue ---
    const int g = lane >> 2, tg = lane & 3;
#pragma unroll
    for (int mt = 0; mt < 4; mt++) {
        const int row = m0 + wm*64 + mt*16 + g;
#pragma unroll
        for (int nt = 0; nt < 8; nt++) {
            const int col = v0 + wn*64 + nt*8 + 2*tg;
            *(float2*)(out + (size_t)row*VV + col) =
                make_float2(d[mt][nt][0], d[mt][nt][1]);
            *(float2*)(out + (size_t)(row + 8)*VV + col) =
                make_float2(d[mt][nt][2], d[mt][nt][3]);
        }
    }
}

// ---------------------------------------------------------------------------
extern "C" void kernel_launch(void* const* d_in, const int* in_sizes, int n_in,
                              void* d_out, int out_size) {
    const float* enc_out = (const float*)d_in[0];
    const int*   tgt     = (const int*)  d_in[1];
    const float* emb     = (const float*)d_in[2];
    const float* Wih0    = (const float*)d_in[3];
    const float* Whh0    = (const float*)d_in[4];
    const float* bih0    = (const float*)d_in[5];
    const float* bhh0    = (const float*)d_in[6];
    const float* Wih1    = (const float*)d_in[7];
    const float* Whh1    = (const float*)d_in[8];
    const float* bih1    = (const float*)d_in[9];
    const float* bhh1    = (const float*)d_in[10];
    const float* Wih2    = (const float*)d_in[11];
    const float* Whh2    = (const float*)d_in[12];
    const float* bih2    = (const float*)d_in[13];
    const float* bhh2    = (const float*)d_in[14];
    const float* enc_w   = (const float*)d_in[15];
    const float* dec_w   = (const float*)d_in[16];
    const float* dec_b   = (const float*)d_in[17];
    const float* out_w   = (const float*)d_in[18];
    float* out = (float*)d_out;

    float *xa, *xb, *xg, *encp, *decp;
    unsigned *Tb, *Bw;
    cudaGetSymbolAddress((void**)&xa,   g_xa);
    cudaGetSymbolAddress((void**)&xb,   g_xb);
    cudaGetSymbolAddress((void**)&xg,   g_xg);
    cudaGetSymbolAddress((void**)&encp, g_encp);
    cudaGetSymbolAddress((void**)&decp, g_decp);
    cudaGetSymbolAddress((void**)&Tb,   g_T);
    cudaGetSymbolAddress((void**)&Bw,   g_bw);

    cudaFuncSetAttribute(k_mma_out, cudaFuncAttributeMaxDynamicSharedMemorySize,
                         SMEM_MMA);

    // 1) embedding + B conversion (independent)
    k_embed<<<(M_SEQ*EE + 255)/256, 256>>>(tgt, emb, xa);
    k_cvtB<<<(VV*JJ/8 + 255)/256, 256>>>(out_w, Bw);

    // 2) layer-0 input gates precompute
    {
        dim3 g((M_SEQ + 63)/64, G4/64);
        k_gemm_abT<<<g, 256>>>(xa, Wih0, bih0, bhh0, xg, M_SEQ, G4, HH);
    }

    // 3) persistent wavefront LSTM
    k_reset<<<1, 32>>>();
    k_lstm_wave<<<GRID_LSTM, 256>>>(xg, Whh0,
                                    Wih1, Whh1, bih1, bhh1,
                                    Wih2, Whh2, bih2, bhh2, xb);

    // 4) enc_p, dec_p projections
    {
        dim3 g((NB*TI)/64, JJ/64);
        k_gemm_abT<<<g, 256>>>(enc_out, enc_w, nullptr, nullptr, encp, NB*TI, JJ, 512);
    }
    {
        dim3 g((M_SEQ + 63)/64, JJ/64);
        k_gemm_abT<<<g, 256>>>(xb, dec_w, dec_b, nullptr, decp, M_SEQ, JJ, HH);
    }

    // 5) materialize fp16 tanh(joint)
    k_tanh<<<M_OUT*64/256, 256>>>(encp, decp, Tb);

    // 6) fp16 HMMA output GEMM
    {
        dim3 g(M_OUT/128, VV/256);
        k_mma_out<<<g, 256, SMEM_MMA>>>(Tb, Bw, out);
    }
}

// round 7
// speedup vs baseline: 4.5288x; 1.2792x over previous
#include <cuda_runtime.h>
#include <cuda_fp16.h>
#include <math.h>
#include <stdint.h>

#define NB  4
#define TI  512
#define TO  64
#define TO1 65
#define VV  1024
#define EE  512
#define HH  512
#define JJ  512
#define G4  2048
#define M_SEQ (NB*TO1)           // 260
#define M_OUT (NB*TI*TO1)        // 133120
#define NTICK (TO1 + 2)
#define GRID_LSTM 96

// Scratch (device globals -- no allocation allowed)
__device__ float g_xa[M_SEQ*EE];
__device__ float g_xb[M_SEQ*HH];
__device__ float g_xg[M_SEQ*G4];
__device__ float g_encp[NB*TI*JJ];
__device__ float g_decp[M_SEQ*JJ];
__device__ float g_h[3][2][NB*HH];
__device__ unsigned g_bar;
__device__ unsigned g_T[M_OUT*256];    // fp16 tanh(enc+dec), fragment-packed (136 MB)
__device__ unsigned g_bw[VV*256];      // fp16 out_w, fragment-packed (1 MB)

// ---------------------------------------------------------------------------
// Embedding with prepended blank token (+ barrier counter reset)
// ---------------------------------------------------------------------------
__global__ void k_embed(const int* __restrict__ tgt, const float* __restrict__ emb,
                        float* __restrict__ x) {
    int idx = blockIdx.x*blockDim.x + threadIdx.x;
    if (idx == 0) g_bar = 0u;
    if (idx >= M_SEQ*EE) return;
    int e = idx & (EE-1);
    int m = idx >> 9;
    int n = m / TO1, t = m - n*TO1;
    int tok = (t == 0) ? 0 : tgt[n*TO + t - 1];
    x[idx] = emb[tok*EE + e];
}

// ---------------------------------------------------------------------------
// C[m,n] = sum_k A[m,k]*B[n,k] + b1[n] + b2[n]   (small/medium GEMMs)
// ---------------------------------------------------------------------------
__global__ void k_gemm_abT(const float* __restrict__ A, const float* __restrict__ B,
                           const float* __restrict__ b1, const float* __restrict__ b2,
                           float* __restrict__ C, int M, int Nn, int K) {
    __shared__ float As[16][64];
    __shared__ float Bs[16][64];
    const int tid = threadIdx.x;
    const int m0 = blockIdx.x*64, n0 = blockIdx.y*64;
    const int lr = tid >> 2;
    const int lk = (tid & 3) << 2;
    const int tx = tid & 15, ty = tid >> 4;
    float acc[4][4] = {};
    const bool mval = (m0 + lr) < M;
    const float* Ap = A + (size_t)(m0+lr)*K + lk;
    const float* Bp = B + (size_t)(n0+lr)*K + lk;

    for (int k0 = 0; k0 < K; k0 += 16) {
        float4 av = make_float4(0.f,0.f,0.f,0.f);
        if (mval) av = *(const float4*)(Ap + k0);
        float4 bv = *(const float4*)(Bp + k0);
        As[lk+0][lr]=av.x; As[lk+1][lr]=av.y; As[lk+2][lr]=av.z; As[lk+3][lr]=av.w;
        Bs[lk+0][lr]=bv.x; Bs[lk+1][lr]=bv.y; Bs[lk+2][lr]=bv.z; Bs[lk+3][lr]=bv.w;
        __syncthreads();
#pragma unroll
        for (int k = 0; k < 16; k++) {
            float4 a4 = *(const float4*)&As[k][ty*4];
            float4 b4 = *(const float4*)&Bs[k][tx*4];
            float aa[4] = {a4.x,a4.y,a4.z,a4.w};
            float bb[4] = {b4.x,b4.y,b4.z,b4.w};
#pragma unroll
            for (int i=0;i<4;i++)
#pragma unroll
                for (int j=0;j<4;j++) acc[i][j] += aa[i]*bb[j];
        }
        __syncthreads();
    }
    float bias[4];
#pragma unroll
    for (int j=0;j<4;j++) {
        int nn = n0 + tx*4 + j;
        bias[j] = (b1 ? b1[nn] : 0.f) + (b2 ? b2[nn] : 0.f);
    }
#pragma unroll
    for (int i=0;i<4;i++) {
        int m = m0 + ty*4 + i;
        if (m < M) {
            float4 o = make_float4(acc[i][0]+bias[0], acc[i][1]+bias[1],
                                   acc[i][2]+bias[2], acc[i][3]+bias[3]);
            *(float4*)&C[(size_t)m*Nn + n0 + tx*4] = o;
        }
    }
}

// ---------------------------------------------------------------------------
// Persistent wavefront LSTM (register-blocked dot8)
// ---------------------------------------------------------------------------
__device__ __forceinline__ float sigf(float x) { return 1.f/(1.f + expf(-x)); }

__device__ __forceinline__ void dot8(const float* __restrict__ Wrow0,
                                     const float* sh, int lane, float acc[8][4]) {
#pragma unroll
    for (int it = 0; it < 4; it++) {
        const int kv4 = (it*32 + lane) * 4;
        float4 h0 = *(const float4*)&sh[0*HH + kv4];
        float4 h1 = *(const float4*)&sh[1*HH + kv4];
        float4 h2 = *(const float4*)&sh[2*HH + kv4];
        float4 h3 = *(const float4*)&sh[3*HH + kv4];
#pragma unroll
        for (int r = 0; r < 8; r++) {
            float4 w = *(const float4*)(Wrow0 + (size_t)r*HH + kv4);
            acc[r][0] += w.x*h0.x + w.y*h0.y + w.z*h0.z + w.w*h0.w;
            acc[r][1] += w.x*h1.x + w.y*h1.y + w.z*h1.z + w.w*h1.w;
            acc[r][2] += w.x*h2.x + w.y*h2.y + w.z*h2.z + w.w*h2.w;
            acc[r][3] += w.x*h3.x + w.y*h3.y + w.z*h3.z + w.w*h3.w;
        }
    }
}

__global__ void __launch_bounds__(256, 1) k_lstm_wave(
    const float* __restrict__ xg0,
    const float* __restrict__ Whh0,
    const float* __restrict__ Wih1, const float* __restrict__ Whh1,
    const float* __restrict__ bih1, const float* __restrict__ bhh1,
    const float* __restrict__ Wih2, const float* __restrict__ Whh2,
    const float* __restrict__ bih2, const float* __restrict__ bhh2,
    float* __restrict__ out_seq)
{
    const int layer = blockIdx.x >> 5;
    const int blk   = blockIdx.x & 31;
    const int j0    = blk * 16;
    const int tid   = threadIdx.x, warp = tid >> 5, lane = tid & 31;

    const float* Whh = (layer==0) ? Whh0 : (layer==1 ? Whh1 : Whh2);
    const float* Wih = (layer==1) ? Wih1 : Wih2;
    const float* bi  = (layer==1) ? bih1 : bih2;
    const float* bh  = (layer==1) ? bhh1 : bhh2;

    __shared__ float sh[NB*HH];
    __shared__ float si[NB*HH];
    __shared__ float gsm[4][NB][16];

    const int rl0 = warp*8;
    const int q   = rl0 >> 4;
    const int jb  = rl0 & 15;
    const float* WhhR = Whh + (size_t)(q*HH + j0 + jb)*HH;
    const float* WihR = Wih + (size_t)(q*HH + j0 + jb)*HH;

    const int eb = tid >> 4, ejj = tid & 15, ej = j0 + ejj;
    float c_reg = 0.f;
    float bias_q[4] = {0.f, 0.f, 0.f, 0.f};
    if (tid < 64 && layer > 0) {
#pragma unroll
        for (int qq = 0; qq < 4; qq++) bias_q[qq] = bi[qq*HH + ej] + bh[qq*HH + ej];
    }

    volatile unsigned* barp = &g_bar;

    for (int tick = 0; tick < NTICK; tick++) {
        const int t = tick - layer;
        if (t >= 0 && t < TO1) {
            const int rp = (tick + 1) & 1;
            const bool havePrev = (t > 0);
            if (havePrev) {
                const float* hp = g_h[layer][rp];
                for (int i = tid; i < NB*HH; i += 256) sh[i] = __ldcg(hp + i);
            }
            if (layer > 0) {
                const float* hi = g_h[layer-1][rp];
                for (int i = tid; i < NB*HH; i += 256) si[i] = __ldcg(hi + i);
            }
            __syncthreads();

            float acc[8][4] = {};
            if (havePrev) dot8(WhhR, sh, lane, acc);
            if (layer > 0) dot8(WihR, si, lane, acc);
#pragma unroll
            for (int r = 0; r < 8; r++) {
#pragma unroll
                for (int off = 16; off; off >>= 1) {
                    acc[r][0] += __shfl_down_sync(0xffffffffu, acc[r][0], off);
                    acc[r][1] += __shfl_down_sync(0xffffffffu, acc[r][1], off);
                    acc[r][2] += __shfl_down_sync(0xffffffffu, acc[r][2], off);
                    acc[r][3] += __shfl_down_sync(0xffffffffu, acc[r][3], off);
                }
            }
            if (lane == 0) {
#pragma unroll
                for (int r = 0; r < 8; r++) {
                    gsm[q][0][jb+r] = acc[r][0];
                    gsm[q][1][jb+r] = acc[r][1];
                    gsm[q][2][jb+r] = acc[r][2];
                    gsm[q][3][jb+r] = acc[r][3];
                }
            }
            __syncthreads();
            if (tid < 64) {
                float p[4];
                if (layer == 0) {
                    const float* xp = xg0 + (size_t)(eb*TO1 + t)*G4;
#pragma unroll
                    for (int qq = 0; qq < 4; qq++) p[qq] = gsm[qq][eb][ejj] + xp[qq*HH + ej];
                } else {
#pragma unroll
                    for (int qq = 0; qq < 4; qq++) p[qq] = gsm[qq][eb][ejj] + bias_q[qq];
                }
                float iv = sigf(p[0]), fv = sigf(p[1]), gv = tanhf(p[2]), ov = sigf(p[3]);
                c_reg = fv*c_reg + iv*gv;
                float h = ov * tanhf(c_reg);
                g_h[layer][tick & 1][eb*HH + ej] = h;
                if (layer == 2) out_seq[(size_t)(eb*TO1 + t)*HH + ej] = h;
                __threadfence();
            }
        }
        __syncthreads();
        if (tid == 0) {
            atomicAdd(&g_bar, 1u);
            unsigned target = (unsigned)gridDim.x * (unsigned)(tick + 1);
            while (*barp < target) { }
        }
        __syncthreads();
    }
}

// ---------------------------------------------------------------------------
// T = fp16(tanh(encp+decp)) written DIRECTLY in m16n8k16 A-fragment order:
//   T[(mtile*32 + ks)*32 + lane] = uint4{a0, a1, a2, a3}
// ---------------------------------------------------------------------------
__device__ __forceinline__ void row_ptrs(int m, const float* __restrict__ encp,
                                         const float* __restrict__ decp,
                                         const float*& ep, const float*& dp) {
    const int n   = m / (TI*TO1);
    const int rem = m - n*(TI*TO1);
    const int t   = rem / TO1;
    const int u   = rem - t*TO1;
    ep = encp + (size_t)(n*TI + t)*JJ;
    dp = decp + (size_t)(n*TO1 + u)*JJ;
}

__global__ void k_tanh(const float* __restrict__ encp, const float* __restrict__ decp,
                       uint4* __restrict__ T) {
    const int idx   = blockIdx.x*256 + threadIdx.x;
    const int lane  = idx & 31;
    const int ks    = (idx >> 5) & 31;
    const int mtile = idx >> 10;
    const int g = lane >> 2, tg = lane & 3;
    const int k0 = ks*16 + 2*tg;

    const float *eA, *dA, *eB, *dB;
    row_ptrs(mtile*16 + g,     encp, decp, eA, dA);
    row_ptrs(mtile*16 + g + 8, encp, decp, eB, dB);

    float2 ea0 = *(const float2*)(eA + k0), ea1 = *(const float2*)(eA + k0 + 8);
    float2 da0 = *(const float2*)(dA + k0), da1 = *(const float2*)(dA + k0 + 8);
    float2 eb0 = *(const float2*)(eB + k0), eb1 = *(const float2*)(eB + k0 + 8);
    float2 db0 = *(const float2*)(dB + k0), db1 = *(const float2*)(dB + k0 + 8);

    __half2 a0 = __floats2half2_rn(tanhf(ea0.x+da0.x), tanhf(ea0.y+da0.y));
    __half2 a1 = __floats2half2_rn(tanhf(eb0.x+db0.x), tanhf(eb0.y+db0.y));
    __half2 a2 = __floats2half2_rn(tanhf(ea1.x+da1.x), tanhf(ea1.y+da1.y));
    __half2 a3 = __floats2half2_rn(tanhf(eb1.x+db1.x), tanhf(eb1.y+db1.y));
    uint4 o;
    o.x = *(unsigned*)&a0; o.y = *(unsigned*)&a1;
    o.z = *(unsigned*)&a2; o.w = *(unsigned*)&a3;
    T[idx] = o;
}

// out_w -> fp16 in B-fragment order:
//   Bw[(vtile*32 + ks)*32 + lane] = uint2{b0, b1},  vtile in [0, VV/8)
__global__ void k_cvtB(const float* __restrict__ w, uint2* __restrict__ o) {
    const int idx   = blockIdx.x*256 + threadIdx.x;
    const int lane  = idx & 31;
    const int ks    = (idx >> 5) & 31;
    const int vtile = idx >> 10;
    const int g = lane >> 2, tg = lane & 3;
    const int k0 = ks*16 + 2*tg;
    const float* wp = w + (size_t)(vtile*8 + g)*JJ;
    float2 f0 = *(const float2*)(wp + k0);
    float2 f1 = *(const float2*)(wp + k0 + 8);
    __half2 b0 = __floats2half2_rn(f0.x, f0.y);
    __half2 b1 = __floats2half2_rn(f1.x, f1.y);
    uint2 v;
    v.x = *(unsigned*)&b0; v.y = *(unsigned*)&b1;
    o[idx] = v;
}

// ---------------------------------------------------------------------------
// SMEM-free fp16 HMMA GEMM: fragments straight from global.
// CTA 128(M) x 256(N); 8 warps 2x4; warp tile 64x64; 32 k16 steps.
// ---------------------------------------------------------------------------
__device__ __forceinline__ void mma16816(float d[4], const unsigned a[4],
                                         const unsigned b[2]) {
    asm volatile(
        "mma.sync.aligned.m16n8k16.row.col.f32.f16.f16.f32 "
        "{%0,%1,%2,%3}, {%4,%5,%6,%7}, {%8,%9}, {%0,%1,%2,%3};"
        : "+f"(d[0]), "+f"(d[1]), "+f"(d[2]), "+f"(d[3])
        : "r"(a[0]), "r"(a[1]), "r"(a[2]), "r"(a[3]), "r"(b[0]), "r"(b[1]));
}

__global__ void __launch_bounds__(256) k_mma_out(
    const uint4* __restrict__ Tf, const uint2* __restrict__ Bf,
    float* __restrict__ out)
{
    const int tid = threadIdx.x;
    const int w = tid >> 5, lane = tid & 31;
    const int wm = w >> 2, wn = w & 3;
    const int m0 = blockIdx.x * 128;
    const int v0 = blockIdx.y * 256;

    const uint4* Ap[4];
#pragma unroll
    for (int mt = 0; mt < 4; mt++)
        Ap[mt] = Tf + ((size_t)(blockIdx.x*8 + wm*4 + mt) * 32) * 32 + lane;
    const uint2* Bp[8];
#pragma unroll
    for (int nt = 0; nt < 8; nt++)
        Bp[nt] = Bf + ((size_t)(blockIdx.y*32 + wn*8 + nt) * 32) * 32 + lane;

    float d[4][8][4];
#pragma unroll
    for (int i = 0; i < 4; i++)
#pragma unroll
        for (int j = 0; j < 8; j++)
#pragma unroll
            for (int k = 0; k < 4; k++) d[i][j][k] = 0.f;

    for (int ks = 0; ks < 32; ks++) {
        unsigned a[4][4], b[8][2];
#pragma unroll
        for (int mt = 0; mt < 4; mt++) {
            uint4 v = Ap[mt][ks*32];
            a[mt][0] = v.x; a[mt][1] = v.y; a[mt][2] = v.z; a[mt][3] = v.w;
        }
#pragma unroll
        for (int nt = 0; nt < 8; nt++) {
            uint2 v = Bp[nt][ks*32];
            b[nt][0] = v.x; b[nt][1] = v.y;
        }
#pragma unroll
        for (int mt = 0; mt < 4; mt++)
#pragma unroll
            for (int nt = 0; nt < 8; nt++)
                mma16816(d[mt][nt], a[mt], b[nt]);
    }

    const int g = lane >> 2, tg = lane & 3;
#pragma unroll
    for (int mt = 0; mt < 4; mt++) {
        const int row = m0 + wm*64 + mt*16 + g;
#pragma unroll
        for (int nt = 0; nt < 8; nt++) {
            const int col = v0 + wn*64 + nt*8 + 2*tg;
            *(float2*)(out + (size_t)row*VV + col) =
                make_float2(d[mt][nt][0], d[mt][nt][1]);
            *(float2*)(out + (size_t)(row + 8)*VV + col) =
                make_float2(d[mt][nt][2], d[mt][nt][3]);
        }
    }
}

// ---------------------------------------------------------------------------
extern "C" void kernel_launch(void* const* d_in, const int* in_sizes, int n_in,
                              void* d_out, int out_size) {
    const float* enc_out = (const float*)d_in[0];
    const int*   tgt     = (const int*)  d_in[1];
    const float* emb     = (const float*)d_in[2];
    const float* Wih0    = (const float*)d_in[3];
    const float* Whh0    = (const float*)d_in[4];
    const float* bih0    = (const float*)d_in[5];
    const float* bhh0    = (const float*)d_in[6];
    const float* Wih1    = (const float*)d_in[7];
    const float* Whh1    = (const float*)d_in[8];
    const float* bih1    = (const float*)d_in[9];
    const float* bhh1    = (const float*)d_in[10];
    const float* Wih2    = (const float*)d_in[11];
    const float* Whh2    = (const float*)d_in[12];
    const float* bih2    = (const float*)d_in[13];
    const float* bhh2    = (const float*)d_in[14];
    const float* enc_w   = (const float*)d_in[15];
    const float* dec_w   = (const float*)d_in[16];
    const float* dec_b   = (const float*)d_in[17];
    const float* out_w   = (const float*)d_in[18];
    float* out = (float*)d_out;

    float *xa, *xb, *xg, *encp, *decp;
    unsigned *Tb, *Bw;
    cudaGetSymbolAddress((void**)&xa,   g_xa);
    cudaGetSymbolAddress((void**)&xb,   g_xb);
    cudaGetSymbolAddress((void**)&xg,   g_xg);
    cudaGetSymbolAddress((void**)&encp, g_encp);
    cudaGetSymbolAddress((void**)&decp, g_decp);
    cudaGetSymbolAddress((void**)&Tb,   g_T);
    cudaGetSymbolAddress((void**)&Bw,   g_bw);

    // 1) embedding (+ g_bar reset) and out_w conversion (independent)
    k_embed<<<(M_SEQ*EE + 255)/256, 256>>>(tgt, emb, xa);
    k_cvtB<<<(VV/8)*32*32/256, 256>>>(out_w, (uint2*)Bw);   // 512 blocks (FIX)

    // 2) layer-0 input gates precompute
    {
        dim3 g((M_SEQ + 63)/64, G4/64);
        k_gemm_abT<<<g, 256>>>(xa, Wih0, bih0, bhh0, xg, M_SEQ, G4, HH);
    }

    // 3) persistent wavefront LSTM
    k_lstm_wave<<<GRID_LSTM, 256>>>(xg, Whh0,
                                    Wih1, Whh1, bih1, bhh1,
                                    Wih2, Whh2, bih2, bhh2, xb);

    // 4) enc_p, dec_p projections
    {
        dim3 g((NB*TI)/64, JJ/64);
        k_gemm_abT<<<g, 256>>>(enc_out, enc_w, nullptr, nullptr, encp, NB*TI, JJ, 512);
    }
    {
        dim3 g((M_SEQ + 63)/64, JJ/64);
        k_gemm_abT<<<g, 256>>>(xb, dec_w, dec_b, nullptr, decp, M_SEQ, JJ, HH);
    }

    // 5) fragment-packed fp16 tanh(joint)
    k_tanh<<<(M_OUT/16)*32*32/256, 256>>>(encp, decp, (uint4*)Tb);

    // 6) SMEM-free fp16 HMMA output GEMM
    {
        dim3 g(M_OUT/128, VV/256);
        k_mma_out<<<g, 256>>>((const uint4*)Tb, (const uint2*)Bw, out);
    }
}